// round 4
// baseline (speedup 1.0000x reference)
#include <cuda_runtime.h>
#include <cuda_bf16.h>

#define T_MAX 4096
#define ACC_BLOCKS 296
#define ACC_THREADS 1024

#define FIX_SCALE 16777216.0f          // 2^24 fixed-point for exp(risk)
#define MASK48 0xFFFFFFFFFFFFull

// Global accumulators. Zero at module load; finalize_kernel re-zeroes them at
// the end of every launch so replays (graph) see clean state with no init kernel.
__device__ unsigned long long g_hist[T_MAX]; // (d_count << 48) | fixed_exp_sum
__device__ double g_evr;                     // sum of risk over events

__global__ void __launch_bounds__(ACC_THREADS)
accum_kernel(const float* __restrict__ risk,
             const void* __restrict__ time_raw,
             const void* __restrict__ event_raw,
             int n)
{
    __shared__ unsigned long long s_hist[T_MAX];
    __shared__ float s_wsum[32];
    __shared__ int s_or;

    if (threadIdx.x == 0) s_or = 0;
    for (int i = threadIdx.x; i < T_MAX; i += ACC_THREADS)
        s_hist[i] = 0ull;

    // Detect element width of `time` (per-block, overlapped with smem init).
    // Times are in [0,4096): int64 layout => every odd 32-bit word is 0.
    // int32 layout => odd words are random times; 2048 samples all-zero has
    // probability ~(1/4096)^2048 ~ 0.
    {
        const int* t32 = (const int*)time_raw;
        int nw = n >> 1;
        if (nw > 2048) nw = 2048;
        int v = 0;
        for (int j = threadIdx.x; j < nw; j += ACC_THREADS)
            v |= t32[2 * j + 1];
        #pragma unroll
        for (int off = 16; off; off >>= 1)
            v |= __shfl_down_sync(0xffffffffu, v, off);
        if ((threadIdx.x & 31) == 0 && v) atomicOr(&s_or, v);
    }
    __syncthreads();
    const int is64 = (s_or == 0);

    const int nchunk = n >> 2;          // 4 elements per chunk
    const int stride = gridDim.x * blockDim.x;
    const int gtid = blockIdx.x * blockDim.x + threadIdx.x;

    const float4* __restrict__ risk4 = (const float4*)risk;

    float evr = 0.0f;

    if (!is64) {
        const int4* __restrict__ time4  = (const int4*)time_raw;
        const int4* __restrict__ event4 = (const int4*)event_raw;
        for (int c = gtid; c < nchunk; c += stride) {
            float4 r = __ldg(&risk4[c]);
            int4 t = __ldg(&time4[c]);
            int4 e = __ldg(&event4[c]);

            int ta = t.x & (T_MAX-1), tb = t.y & (T_MAX-1);
            int tc = t.z & (T_MAX-1), td = t.w & (T_MAX-1);

            unsigned long long va = (unsigned long long)(__expf(r.x) * FIX_SCALE + 0.5f);
            unsigned long long vb = (unsigned long long)(__expf(r.y) * FIX_SCALE + 0.5f);
            unsigned long long vc = (unsigned long long)(__expf(r.z) * FIX_SCALE + 0.5f);
            unsigned long long vd = (unsigned long long)(__expf(r.w) * FIX_SCALE + 0.5f);

            if (e.x) { va += (1ull << 48); evr += r.x; }
            if (e.y) { vb += (1ull << 48); evr += r.y; }
            if (e.z) { vc += (1ull << 48); evr += r.z; }
            if (e.w) { vd += (1ull << 48); evr += r.w; }

            atomicAdd(&s_hist[ta], va);
            atomicAdd(&s_hist[tb], vb);
            atomicAdd(&s_hist[tc], vc);
            atomicAdd(&s_hist[td], vd);
        }
        int rem = n & 3;
        if (blockIdx.x == 0 && threadIdx.x < rem) {
            int i = (nchunk << 2) + threadIdx.x;
            const int* t32 = (const int*)time_raw;
            const int* e32 = (const int*)event_raw;
            float r = __ldg(&risk[i]);
            int t = t32[i] & (T_MAX-1);
            unsigned long long v = (unsigned long long)(__expf(r) * FIX_SCALE + 0.5f);
            if (e32[i]) { v += (1ull << 48); evr += r; }
            atomicAdd(&s_hist[t], v);
        }
    } else {
        const int4* __restrict__ time4  = (const int4*)time_raw;   // 2 int64 per int4
        const int4* __restrict__ event4 = (const int4*)event_raw;
        for (int c = gtid; c < nchunk; c += stride) {
            float4 r = __ldg(&risk4[c]);
            int4 t0 = __ldg(&time4[2*c]);
            int4 t1 = __ldg(&time4[2*c + 1]);
            int4 e0 = __ldg(&event4[2*c]);
            int4 e1 = __ldg(&event4[2*c + 1]);

            int ta = t0.x & (T_MAX-1), tb = t0.z & (T_MAX-1);
            int tc = t1.x & (T_MAX-1), td = t1.z & (T_MAX-1);

            unsigned long long va = (unsigned long long)(__expf(r.x) * FIX_SCALE + 0.5f);
            unsigned long long vb = (unsigned long long)(__expf(r.y) * FIX_SCALE + 0.5f);
            unsigned long long vc = (unsigned long long)(__expf(r.z) * FIX_SCALE + 0.5f);
            unsigned long long vd = (unsigned long long)(__expf(r.w) * FIX_SCALE + 0.5f);

            if (e0.x) { va += (1ull << 48); evr += r.x; }
            if (e0.z) { vb += (1ull << 48); evr += r.y; }
            if (e1.x) { vc += (1ull << 48); evr += r.z; }
            if (e1.z) { vd += (1ull << 48); evr += r.w; }

            atomicAdd(&s_hist[ta], va);
            atomicAdd(&s_hist[tb], vb);
            atomicAdd(&s_hist[tc], vc);
            atomicAdd(&s_hist[td], vd);
        }
        int rem = n & 3;
        if (blockIdx.x == 0 && threadIdx.x < rem) {
            int i = (nchunk << 2) + threadIdx.x;
            const long long* t64 = (const long long*)time_raw;
            const long long* e64 = (const long long*)event_raw;
            float r = __ldg(&risk[i]);
            int t = (int)t64[i] & (T_MAX-1);
            unsigned long long v = (unsigned long long)(__expf(r) * FIX_SCALE + 0.5f);
            if (e64[i]) { v += (1ull << 48); evr += r; }
            atomicAdd(&s_hist[t], v);
        }
    }

    // Reduce evr: warp shuffle, then cross-warp via shared
    int lane = threadIdx.x & 31, wid = threadIdx.x >> 5;
    #pragma unroll
    for (int off = 16; off; off >>= 1)
        evr += __shfl_down_sync(0xffffffffu, evr, off);
    if (lane == 0) s_wsum[wid] = evr;

    __syncthreads();   // covers s_wsum visibility AND s_hist completion

    if (wid == 0) {
        float s = (lane < (ACC_THREADS / 32)) ? s_wsum[lane] : 0.0f;
        #pragma unroll
        for (int off = 16; off; off >>= 1)
            s += __shfl_down_sync(0xffffffffu, s, off);
        if (lane == 0) atomicAdd(&g_evr, (double)s);
    }

    // Flush block-private histogram to global
    for (int i = threadIdx.x; i < T_MAX; i += ACC_THREADS) {
        unsigned long long v = s_hist[i];
        if (v) atomicAdd(&g_hist[i], v);
    }
}

// Single block, 1024 threads. j = 4095 - t (reversed index) so the suffix
// sum over time becomes an inclusive prefix scan over j.
// Float scan + logf; final 4096-term accumulation in double.
// At the end, re-zero global state for the next launch/replay.
__global__ void __launch_bounds__(1024)
finalize_kernel(float* __restrict__ out)
{
    __shared__ float s_scan[32];
    __shared__ double s_acc[32];
    __shared__ int s_totd[32];

    const int tid = threadIdx.x;
    const int lane = tid & 31, wid = tid >> 5;

    int dloc[4];
    float local[4];
    float run = 0.0f;
    #pragma unroll
    for (int k = 0; k < 4; k++) {
        int t = (T_MAX - 1) - (tid * 4 + k);
        unsigned long long h = g_hist[t];
        dloc[k] = (int)(h >> 48);
        run += (float)((double)(h & MASK48) * (1.0 / 16777216.0));
        local[k] = run;
    }

    // Inclusive scan of per-thread totals (warp shuffle then cross-warp)
    float v = run;
    #pragma unroll
    for (int off = 1; off < 32; off <<= 1) {
        float nv = __shfl_up_sync(0xffffffffu, v, off);
        if (lane >= off) v += nv;
    }
    if (lane == 31) s_scan[wid] = v;
    __syncthreads();
    if (wid == 0) {
        float w = s_scan[lane];
        #pragma unroll
        for (int off = 1; off < 32; off <<= 1) {
            float nw = __shfl_up_sync(0xffffffffu, w, off);
            if (lane >= off) w += nw;
        }
        s_scan[lane] = w;
    }
    __syncthreads();

    float excl = (v - run) + (wid > 0 ? s_scan[wid - 1] : 0.0f);

    double acc = 0.0;
    int totd = 0;
    #pragma unroll
    for (int k = 0; k < 4; k++) {
        int d = dloc[k];
        if (d) {
            acc += (double)((float)d * logf(excl + local[k]));
            totd += d;
        }
    }

    // Re-zero this thread's g_hist slots for the next launch (each slot is
    // read and zeroed by the same thread — no race).
    #pragma unroll
    for (int k = 0; k < 4; k++)
        g_hist[(T_MAX - 1) - (tid * 4 + k)] = 0ull;

    // Block reduce acc (double) and totd (int)
    #pragma unroll
    for (int off = 16; off; off >>= 1) {
        acc  += __shfl_down_sync(0xffffffffu, acc, off);
        totd += __shfl_down_sync(0xffffffffu, totd, off);
    }
    if (lane == 0) { s_acc[wid] = acc; s_totd[wid] = totd; }
    __syncthreads();
    if (wid == 0) {
        double a = s_acc[lane];
        int d = s_totd[lane];
        #pragma unroll
        for (int off = 16; off; off >>= 1) {
            a += __shfl_down_sync(0xffffffffu, a, off);
            d += __shfl_down_sync(0xffffffffu, d, off);
        }
        if (lane == 0) {
            out[0] = (d > 0) ? (float)(a - g_evr) : 0.0f;
            g_evr = 0.0;   // reset for next launch
        }
    }
}

extern "C" void kernel_launch(void* const* d_in, const int* in_sizes, int n_in,
                              void* d_out, int out_size)
{
    const float* risk  = (const float*)d_in[0];
    const void*  time  = d_in[1];
    const void*  event = d_in[2];
    int n = in_sizes[0];

    accum_kernel<<<ACC_BLOCKS, ACC_THREADS>>>(risk, time, event, n);
    finalize_kernel<<<1, 1024>>>((float*)d_out);
}